// round 7
// baseline (speedup 1.0000x reference)
#include <cuda_runtime.h>
#include <cuda_bf16.h>

#define B_    8
#define NUM_  128
#define L_    (NUM_ * NUM_)     // 16384
#define H_    8
#define TOPK_ 4
#define NROWS_ (B_ * NUM_)      // 1024 (b,i) rows
#define NC_    8                // chunks per row (16 j each)

// Scratch (allocation-free rule: __device__ globals)
__device__ float    g_cval[NROWS_ * H_ * NC_ * TOPK_];    // 1 MB candidate values
__device__ unsigned g_cidx[NROWS_ * H_ * NC_];            // packed 4x8bit local idx
__device__ unsigned g_maskbits[4];                        // 128-bit column mask

// ---------------------------------------------------------------------------
// Kernel 1: block = (b,i,chunk). Cosine+relu for 16 j x 8 h, multiply by roi,
// write DIRECTLY to out, emit per-head per-chunk top-4 candidates.
// Warp w handles j = 2w, 2w+1; lane layout: head = lane>>2, sub = lane&3.
// ---------------------------------------------------------------------------
__global__ __launch_bounds__(256, 6) void fused_kernel(
    const float4* __restrict__ q4, const float4* __restrict__ k4,
    const float* __restrict__ roi, float* __restrict__ out)
{
    __shared__ float s_attn[16 * 9];            // local j x head, pitch 9

    const int blk  = blockIdx.x;
    const int bi   = blk >> 3;                  // (b,i) row
    const int chk  = blk & 7;                   // 16-j chunk
    const int tid  = threadIdx.x;
    const int warp = tid >> 5;
    const int lane = tid & 31;
    const int head = lane >> 2;
    const int sub  = lane & 3;

    if (blk == 0 && tid < 4) g_maskbits[tid] = 0u;   // reset per replay

    const size_t rowBase = (size_t)bi * (NUM_ * 128) + (size_t)chk * (16 * 128);

    // ---- warp computes its two j's: 16 LDG.128 front-batched ----
    {
        const int jl0 = warp * 2;
        const size_t base0 = rowBase + (size_t)jl0 * 128;
        const size_t base1 = base0 + 128;

        float dot0 = 0.f, qq0 = 0.f, kk0 = 0.f;
        float dot1 = 0.f, qq1 = 0.f, kk1 = 0.f;
        #pragma unroll
        for (int t = 0; t < 4; ++t) {
            const int idx = head * 16 + t * 4 + sub;
            const float4 qa = __ldcs(&q4[base0 + idx]);
            const float4 ka = __ldcs(&k4[base0 + idx]);
            const float4 qb = __ldcs(&q4[base1 + idx]);
            const float4 kb = __ldcs(&k4[base1 + idx]);
            dot0 += qa.x*ka.x + qa.y*ka.y + qa.z*ka.z + qa.w*ka.w;
            qq0  += qa.x*qa.x + qa.y*qa.y + qa.z*qa.z + qa.w*qa.w;
            kk0  += ka.x*ka.x + ka.y*ka.y + ka.z*ka.z + ka.w*ka.w;
            dot1 += qb.x*kb.x + qb.y*kb.y + qb.z*kb.z + qb.w*kb.w;
            qq1  += qb.x*qb.x + qb.y*qb.y + qb.z*qb.z + qb.w*qb.w;
            kk1  += kb.x*kb.x + kb.y*kb.y + kb.z*kb.z + kb.w*kb.w;
        }
        #pragma unroll
        for (int off = 1; off <= 2; off <<= 1) {
            dot0 += __shfl_xor_sync(0xffffffffu, dot0, off);
            qq0  += __shfl_xor_sync(0xffffffffu, qq0,  off);
            kk0  += __shfl_xor_sync(0xffffffffu, kk0,  off);
            dot1 += __shfl_xor_sync(0xffffffffu, dot1, off);
            qq1  += __shfl_xor_sync(0xffffffffu, qq1,  off);
            kk1  += __shfl_xor_sync(0xffffffffu, kk1,  off);
        }
        if (sub == 0) {
            float d0 = fmaxf(sqrtf(qq0) * sqrtf(kk0), 1e-8f);
            float d1 = fmaxf(sqrtf(qq1) * sqrtf(kk1), 1e-8f);
            s_attn[jl0 * 9 + head]       = fmaxf(dot0 / d0, 0.0f);
            s_attn[(jl0 + 1) * 9 + head] = fmaxf(dot1 / d1, 0.0f);
        }
    }
    __syncthreads();

    // ---- writeback: out[b,i,j,h] = attn * roi[b,i,j] (mask applied later) ----
    if (tid < 128) {
        const int jl = tid >> 3;                          // local j
        const float s = __ldg(&roi[bi * NUM_ + chk * 16 + jl]);
        const size_t gbase = (size_t)bi * (NUM_ * H_) + (size_t)chk * (16 * H_);
        out[gbase + tid] = s_attn[jl * 9 + (tid & 7)] * s;
    }

    // ---- per-head top-4 within this 16-j chunk: warp w = head w ----
    {
        float v;
        int   jl;
        if (lane < 16) { v = s_attn[lane * 9 + warp]; jl = lane; }
        else           { v = -1e30f;                  jl = 255;  }
        unsigned packed = 0;
        const int rbase = ((bi * H_ + warp) * NC_ + chk) * TOPK_;
        #pragma unroll
        for (int r = 0; r < TOPK_; ++r) {
            float bv = v; int bj = jl;
            #pragma unroll
            for (int off = 16; off > 0; off >>= 1) {
                const float ov = __shfl_xor_sync(0xffffffffu, bv, off);
                const int   oj = __shfl_xor_sync(0xffffffffu, bj, off);
                if (ov > bv || (ov == bv && oj < bj)) { bv = ov; bj = oj; }
            }
            packed |= ((unsigned)bj) << (8 * r);
            if (jl == bj) v = -1e30f;           // remove winner
            if (lane == 0) g_cval[rbase + r] = bv;
        }
        if (lane == 0) g_cidx[(bi * H_ + warp) * NC_ + chk] = packed;
    }
}

// ---------------------------------------------------------------------------
// Kernel 2: merge. One thread per (b,i,h): top-4 of 32 candidates, union bits.
// ---------------------------------------------------------------------------
__global__ __launch_bounds__(256) void merge_kernel()
{
    __shared__ unsigned s_bits[4];
    const int tid = threadIdx.x;
    if (tid < 4) s_bits[tid] = 0u;
    __syncthreads();

    const int r = blockIdx.x * blockDim.x + tid;   // 0..8191
    float vv[32];
    int   jj[32];
    const float4* cv4 = (const float4*)&g_cval[r * NC_ * TOPK_];
    #pragma unroll
    for (int q = 0; q < NC_; ++q) {
        const float4 v = cv4[q];
        const unsigned w = g_cidx[r * NC_ + q];
        vv[q*4+0] = v.x; jj[q*4+0] = q*16 + ((w      ) & 255);
        vv[q*4+1] = v.y; jj[q*4+1] = q*16 + ((w >>  8) & 255);
        vv[q*4+2] = v.z; jj[q*4+2] = q*16 + ((w >> 16) & 255);
        vv[q*4+3] = v.w; jj[q*4+3] = q*16 + ((w >> 24) & 255);
    }
    unsigned bits0 = 0, bits1 = 0, bits2 = 0, bits3 = 0;
    #pragma unroll
    for (int rr = 0; rr < TOPK_; ++rr) {
        float bv = vv[0]; int bj = jj[0]; int bt = 0;
        #pragma unroll
        for (int t = 1; t < 32; ++t)
            if (vv[t] > bv || (vv[t] == bv && jj[t] < bj)) { bv = vv[t]; bj = jj[t]; bt = t; }
        if (bj < 32)       bits0 |= 1u << bj;
        else if (bj < 64)  bits1 |= 1u << (bj - 32);
        else if (bj < 96)  bits2 |= 1u << (bj - 64);
        else               bits3 |= 1u << (bj - 96);
        vv[bt] = -1e30f;
    }
    if (bits0) atomicOr(&s_bits[0], bits0);
    if (bits1) atomicOr(&s_bits[1], bits1);
    if (bits2) atomicOr(&s_bits[2], bits2);
    if (bits3) atomicOr(&s_bits[3], bits3);
    __syncthreads();
    if (tid < 4 && s_bits[tid]) atomicOr(&g_maskbits[tid], s_bits[tid]);
}

// ---------------------------------------------------------------------------
// Kernel 3: fixup. Block j: if mask[j]==0, zero out[:, :, j, :]. Near-nop
// when the union mask is full (common case); exact in all cases.
// ---------------------------------------------------------------------------
__global__ __launch_bounds__(256) void fixup_kernel(float4* __restrict__ out)
{
    const int j = blockIdx.x;
    if ((g_maskbits[j >> 5] >> (j & 31)) & 1u) return;   // column survives

    const float4 z = make_float4(0.f, 0.f, 0.f, 0.f);
    #pragma unroll
    for (int t = 0; t < 4; ++t) {
        const int bi = threadIdx.x + t * 256;            // 0..1023
        const size_t base = ((size_t)bi * NUM_ + j) * 2; // float4 units
        out[base]     = z;
        out[base + 1] = z;
    }
}

// ---------------------------------------------------------------------------
extern "C" void kernel_launch(void* const* d_in, const int* in_sizes, int n_in,
                              void* d_out, int out_size)
{
    const float4* q4  = (const float4*)d_in[0];
    const float4* k4  = (const float4*)d_in[1];
    const float*  roi = (const float*)d_in[2];
    float*        out = (float*)d_out;

    fused_kernel<<<NROWS_ * NC_, 256>>>(q4, k4, roi, out);  // 8192 blocks
    merge_kernel<<<(NROWS_ * H_) / 256, 256>>>();           // 32 blocks
    fixup_kernel<<<NUM_, 256>>>((float4*)out);              // 128 blocks
}

// round 8
// speedup vs baseline: 1.0194x; 1.0194x over previous
#include <cuda_runtime.h>
#include <cuda_bf16.h>

#define B_    8
#define NUM_  128
#define L_    (NUM_ * NUM_)     // 16384
#define H_    8
#define TOPK_ 4
#define NROWS_ (B_ * NUM_)      // 1024 (b,i) rows
#define NC_    8                // chunks per row (16 j each)

// Scratch (allocation-free rule: __device__ globals)
__device__ float    g_cval[NROWS_ * H_ * NC_ * TOPK_];    // 1 MB candidate values
__device__ unsigned g_cidx[NROWS_ * H_ * NC_];            // packed 4x8bit local idx
__device__ unsigned g_maskbits[4];                        // 128-bit column mask

// ---------------------------------------------------------------------------
// Kernel 1: block = (b,i,chunk). Cosine+relu for 16 j x 8 h, multiply by roi,
// write DIRECTLY to out, emit per-head per-chunk top-4 candidates.
// Warp w handles j = 2w, 2w+1; lane layout: head = lane>>2, sub = lane&3.
// ---------------------------------------------------------------------------
__global__ __launch_bounds__(256, 6) void fused_kernel(
    const float4* __restrict__ q4, const float4* __restrict__ k4,
    const float* __restrict__ roi, float* __restrict__ out)
{
    __shared__ float s_attn[16 * 9];            // local j x head, pitch 9

    const int blk  = blockIdx.x;
    const int bi   = blk >> 3;                  // (b,i) row
    const int chk  = blk & 7;                   // 16-j chunk
    const int tid  = threadIdx.x;
    const int warp = tid >> 5;
    const int lane = tid & 31;
    const int head = lane >> 2;
    const int sub  = lane & 3;

    if (blk == 0 && tid < 4) g_maskbits[tid] = 0u;   // reset per replay

    const size_t rowBase = (size_t)bi * (NUM_ * 128) + (size_t)chk * (16 * 128);

    // ---- warp computes its two j's: 16 LDG.128 front-batched ----
    {
        const int jl0 = warp * 2;
        const size_t base0 = rowBase + (size_t)jl0 * 128;
        const size_t base1 = base0 + 128;

        float dot0 = 0.f, qq0 = 0.f, kk0 = 0.f;
        float dot1 = 0.f, qq1 = 0.f, kk1 = 0.f;
        #pragma unroll
        for (int t = 0; t < 4; ++t) {
            const int idx = head * 16 + t * 4 + sub;
            const float4 qa = __ldcs(&q4[base0 + idx]);
            const float4 ka = __ldcs(&k4[base0 + idx]);
            const float4 qb = __ldcs(&q4[base1 + idx]);
            const float4 kb = __ldcs(&k4[base1 + idx]);
            dot0 += qa.x*ka.x + qa.y*ka.y + qa.z*ka.z + qa.w*ka.w;
            qq0  += qa.x*qa.x + qa.y*qa.y + qa.z*qa.z + qa.w*qa.w;
            kk0  += ka.x*ka.x + ka.y*ka.y + ka.z*ka.z + ka.w*ka.w;
            dot1 += qb.x*kb.x + qb.y*kb.y + qb.z*kb.z + qb.w*kb.w;
            qq1  += qb.x*qb.x + qb.y*qb.y + qb.z*qb.z + qb.w*qb.w;
            kk1  += kb.x*kb.x + kb.y*kb.y + kb.z*kb.z + kb.w*kb.w;
        }
        #pragma unroll
        for (int off = 1; off <= 2; off <<= 1) {
            dot0 += __shfl_xor_sync(0xffffffffu, dot0, off);
            qq0  += __shfl_xor_sync(0xffffffffu, qq0,  off);
            kk0  += __shfl_xor_sync(0xffffffffu, kk0,  off);
            dot1 += __shfl_xor_sync(0xffffffffu, dot1, off);
            qq1  += __shfl_xor_sync(0xffffffffu, qq1,  off);
            kk1  += __shfl_xor_sync(0xffffffffu, kk1,  off);
        }
        if (sub == 0) {
            float d0 = fmaxf(sqrtf(qq0) * sqrtf(kk0), 1e-8f);
            float d1 = fmaxf(sqrtf(qq1) * sqrtf(kk1), 1e-8f);
            s_attn[jl0 * 9 + head]       = fmaxf(dot0 / d0, 0.0f);
            s_attn[(jl0 + 1) * 9 + head] = fmaxf(dot1 / d1, 0.0f);
        }
    }
    __syncthreads();

    // ---- writeback: out[b,i,j,h] = attn * roi[b,i,j] (mask applied later) ----
    if (tid < 128) {
        const int jl = tid >> 3;                          // local j
        const float s = __ldg(&roi[bi * NUM_ + chk * 16 + jl]);
        const size_t gbase = (size_t)bi * (NUM_ * H_) + (size_t)chk * (16 * H_);
        out[gbase + tid] = s_attn[jl * 9 + (tid & 7)] * s;
    }

    // ---- per-head top-4 within this 16-j chunk: warp w = head w ----
    {
        float v;
        int   jl;
        if (lane < 16) { v = s_attn[lane * 9 + warp]; jl = lane; }
        else           { v = -1e30f;                  jl = 255;  }
        unsigned packed = 0;
        const int rbase = ((bi * H_ + warp) * NC_ + chk) * TOPK_;
        #pragma unroll
        for (int r = 0; r < TOPK_; ++r) {
            float bv = v; int bj = jl;
            #pragma unroll
            for (int off = 16; off > 0; off >>= 1) {
                const float ov = __shfl_xor_sync(0xffffffffu, bv, off);
                const int   oj = __shfl_xor_sync(0xffffffffu, bj, off);
                if (ov > bv || (ov == bv && oj < bj)) { bv = ov; bj = oj; }
            }
            packed |= ((unsigned)bj) << (8 * r);
            if (jl == bj) v = -1e30f;           // remove winner
            if (lane == 0) g_cval[rbase + r] = bv;
        }
        if (lane == 0) g_cidx[(bi * H_ + warp) * NC_ + chk] = packed;
    }
}

// ---------------------------------------------------------------------------
// Kernel 2: merge. One WARP per (b,i,h) row: lane = one of 32 candidates,
// 4 rounds of warp-argmax (val desc, j asc), union bits. No local arrays.
// ---------------------------------------------------------------------------
__global__ __launch_bounds__(256) void merge_kernel()
{
    __shared__ unsigned s_bits[4];
    const int tid  = threadIdx.x;
    const int warp = tid >> 5;
    const int lane = tid & 31;
    if (tid < 4) s_bits[tid] = 0u;
    __syncthreads();

    const int r = blockIdx.x * 8 + warp;        // row 0..8191
    // lane's candidate: value coalesced, index unpacked from packed word
    float v = g_cval[r * (NC_ * TOPK_) + lane];
    const unsigned w = g_cidx[r * NC_ + (lane >> 2)];
    const int j = (lane >> 2) * 16 + (int)((w >> (8 * (lane & 3))) & 255u);

    #pragma unroll
    for (int rr = 0; rr < TOPK_; ++rr) {
        float bv = v; int bj = j;
        #pragma unroll
        for (int off = 16; off > 0; off >>= 1) {
            const float ov = __shfl_xor_sync(0xffffffffu, bv, off);
            const int   oj = __shfl_xor_sync(0xffffffffu, bj, off);
            if (ov > bv || (ov == bv && oj < bj)) { bv = ov; bj = oj; }
        }
        if (lane == 0) atomicOr(&s_bits[bj >> 5], 1u << (bj & 31));
        if (j == bj) v = -1e30f;                // drop winner (global j unique)
    }
    __syncthreads();
    if (tid < 4 && s_bits[tid]) atomicOr(&g_maskbits[tid], s_bits[tid]);
}

// ---------------------------------------------------------------------------
// Kernel 3: fixup. Block j: if mask[j]==0, zero out[:, :, j, :]. Near-nop
// when the union mask is full (common case); exact in all cases.
// ---------------------------------------------------------------------------
__global__ __launch_bounds__(256) void fixup_kernel(float4* __restrict__ out)
{
    const int j = blockIdx.x;
    if ((g_maskbits[j >> 5] >> (j & 31)) & 1u) return;   // column survives

    const float4 z = make_float4(0.f, 0.f, 0.f, 0.f);
    #pragma unroll
    for (int t = 0; t < 4; ++t) {
        const int bi = threadIdx.x + t * 256;            // 0..1023
        const size_t base = ((size_t)bi * NUM_ + j) * 2; // float4 units
        out[base]     = z;
        out[base + 1] = z;
    }
}

// ---------------------------------------------------------------------------
extern "C" void kernel_launch(void* const* d_in, const int* in_sizes, int n_in,
                              void* d_out, int out_size)
{
    const float4* q4  = (const float4*)d_in[0];
    const float4* k4  = (const float4*)d_in[1];
    const float*  roi = (const float*)d_in[2];
    float*        out = (float*)d_out;

    fused_kernel<<<NROWS_ * NC_, 256>>>(q4, k4, roi, out);  // 8192 blocks
    merge_kernel<<<NROWS_ * H_ / 8, 256>>>();               // 1024 blocks
    fixup_kernel<<<NUM_, 256>>>((float4*)out);              // 128 blocks
}